// round 1
// baseline (speedup 1.0000x reference)
#include <cuda_runtime.h>
#include <math.h>

// Problem constants (fixed by the dataset)
#define NN 50000
#define EE 800000

// ---------------- scratch (static device globals; no allocation) ----------
__device__ float g_g1[(size_t)NN * 384];  // [xl1 | xr1 | res1]
__device__ float g_h1[(size_t)NN * 128];
__device__ float g_g2[(size_t)NN * 256];  // [xl2 | xr2]
__device__ float g_h2[(size_t)NN * 128];
__device__ float g_g3[(size_t)NN * 141];  // [xl3 | xr3 | res3]
__device__ float g_w1[100 * 384];
__device__ float g_w2[128 * 256];
__device__ float g_w3[128 * 141];
__device__ int g_cnt[NN];
__device__ int g_offs[NN + 1];
__device__ int g_cur[NN];
__device__ int g_csr[EE];

// ---------------- CSR construction ----------------------------------------
__global__ void hist_kernel(const int* __restrict__ dst, int* __restrict__ cnt, int e) {
    int i = blockIdx.x * blockDim.x + threadIdx.x;
    if (i < e) atomicAdd(&cnt[dst[i]], 1);
}

__global__ void scan_kernel(const int* __restrict__ cnt, int* __restrict__ offs,
                            int* __restrict__ cur, int n) {
    const int T = 1024;
    int tid = threadIdx.x;
    int chunk = (n + T - 1) / T;
    int start = tid * chunk;
    int end = min(start + chunk, n);
    int s = 0;
    for (int i = start; i < end; ++i) s += cnt[i];
    __shared__ int sh[T];
    sh[tid] = s;
    __syncthreads();
    for (int off = 1; off < T; off <<= 1) {
        int t = 0;
        if (tid >= off) t = sh[tid - off];
        __syncthreads();
        if (tid >= off) sh[tid] += t;
        __syncthreads();
    }
    int incl = sh[tid];
    int run = incl - s;  // exclusive
    for (int i = start; i < end; ++i) {
        offs[i] = run;
        cur[i] = run;
        run += cnt[i];
    }
    if (tid == T - 1) offs[n] = run;
}

__global__ void scatter_kernel(const int* __restrict__ src, const int* __restrict__ dst,
                               int* __restrict__ cur, int* __restrict__ csr, int e) {
    int i = blockIdx.x * blockDim.x + threadIdx.x;
    if (i < e) {
        int p = atomicAdd(&cur[dst[i]], 1);
        csr[p] = src[i];
    }
}

// ---------------- weight packing: dst[k*(Ca+Cb+Cc)+c] = concat ------------
__global__ void pack3_kernel(float* __restrict__ dstp,
                             const float* __restrict__ a, const float* __restrict__ b,
                             const float* __restrict__ c,
                             int K, int Ca, int Cb, int Cc) {
    int C = Ca + Cb + Cc;
    int total = K * C;
    for (int idx = blockIdx.x * blockDim.x + threadIdx.x; idx < total;
         idx += gridDim.x * blockDim.x) {
        int k = idx / C;
        int col = idx - k * C;
        float v;
        if (col < Ca) v = a[k * Ca + col];
        else if (col < Ca + Cb) v = b[k * Cb + (col - Ca)];
        else v = c[k * Cc + (col - Ca - Cb)];
        dstp[idx] = v;
    }
}

// ---------------- fp32 SGEMM: C[M,N] = A[M,K] @ B[K,N], row-major ---------
__global__ void __launch_bounds__(256)
sgemm_kernel(const float* __restrict__ A, const float* __restrict__ B,
             float* __restrict__ C, int M, int N, int K) {
    __shared__ float As[8][128];
    __shared__ float Bs[8][128];
    int tid = threadIdx.x;
    int brow = blockIdx.y * 128;
    int bcol = blockIdx.x * 128;
    int tr = (tid / 16) * 8;
    int tc = (tid % 16) * 8;

    float acc[8][8];
#pragma unroll
    for (int i = 0; i < 8; ++i)
#pragma unroll
        for (int j = 0; j < 8; ++j) acc[i][j] = 0.f;

    int arow = tid >> 1;          // 0..127
    int ak = (tid & 1) * 4;       // 0 or 4
    int bk = tid >> 5;            // 0..7
    int bc = (tid & 31) * 4;      // 0..124

    for (int k0 = 0; k0 < K; k0 += 8) {
#pragma unroll
        for (int q = 0; q < 4; ++q) {
            int kk = ak + q;
            float v = 0.f;
            if (brow + arow < M && k0 + kk < K) v = A[(size_t)(brow + arow) * K + k0 + kk];
            As[kk][arow] = v;
        }
#pragma unroll
        for (int q = 0; q < 4; ++q) {
            float v = 0.f;
            if (k0 + bk < K && bcol + bc + q < N) v = B[(size_t)(k0 + bk) * N + bcol + bc + q];
            Bs[bk][bc + q] = v;
        }
        __syncthreads();
#pragma unroll
        for (int kk = 0; kk < 8; ++kk) {
            float ra[8], rb[8];
#pragma unroll
            for (int i = 0; i < 8; ++i) ra[i] = As[kk][tr + i];
#pragma unroll
            for (int j = 0; j < 8; ++j) rb[j] = Bs[kk][tc + j];
#pragma unroll
            for (int i = 0; i < 8; ++i)
#pragma unroll
                for (int j = 0; j < 8; ++j) acc[i][j] = fmaf(ra[i], rb[j], acc[i][j]);
        }
        __syncthreads();
    }
#pragma unroll
    for (int i = 0; i < 8; ++i) {
        int r = brow + tr + i;
        if (r >= M) continue;
#pragma unroll
        for (int j = 0; j < 8; ++j) {
            int cidx = bcol + tc + j;
            if (cidx < N) C[(size_t)r * N + cidx] = acc[i][j];
        }
    }
}

// ---------------- GATv2 edge phase: one warp per destination node ---------
// xlr: [n, ld] rows containing [xl (NH*CH) | xr (NH*CH) | ...]
// Fused epilogue: + bias + residual (+res_b) -> BN -> optional ReLU.
template <int NH, int CH>
__global__ void gat_kernel(const float* __restrict__ xlr, int ld,
                           const float* __restrict__ att,
                           const float* __restrict__ bias,
                           const float* __restrict__ resid, int ldr,
                           const float* __restrict__ res_b,
                           const float* __restrict__ bn_g, const float* __restrict__ bn_b,
                           const float* __restrict__ bn_m, const float* __restrict__ bn_v,
                           float* __restrict__ out, int ldo, int do_relu,
                           const int* __restrict__ offs, const int* __restrict__ csr,
                           int n) {
    int warp = (blockIdx.x * blockDim.x + threadIdx.x) >> 5;
    int lane = threadIdx.x & 31;
    if (warp >= n) return;
    const int i = warp;
    constexpr int NJ = (CH + 31) / 32;
    constexpr int F = NH * CH;
    const float* xl = xlr;
    const float* xr = xlr + F;

    float xrv[NH][NJ], attv[NH][NJ], acc[NH][NJ], mh[NH], dh[NH];
#pragma unroll
    for (int h = 0; h < NH; ++h) {
        mh[h] = -INFINITY;
        dh[h] = 0.f;
#pragma unroll
        for (int j = 0; j < NJ; ++j) {
            int c = lane + 32 * j;
            bool ok = (c < CH);
            xrv[h][j] = ok ? xr[(size_t)i * ld + h * CH + c] : 0.f;
            attv[h][j] = ok ? att[h * CH + c] : 0.f;
            acc[h][j] = 0.f;
        }
    }

    int e0 = offs[i], e1 = offs[i + 1];
    for (int t = e0; t <= e1; ++t) {  // t == e1 -> implicit self-loop
        int s = (t < e1) ? csr[t] : i;
        float xs[NH][NJ], part[NH];
#pragma unroll
        for (int h = 0; h < NH; ++h) {
            part[h] = 0.f;
#pragma unroll
            for (int j = 0; j < NJ; ++j) {
                int c = lane + 32 * j;
                float v = (c < CH) ? xl[(size_t)s * ld + h * CH + c] : 0.f;
                xs[h][j] = v;
                float u = v + xrv[h][j];
                u = (u > 0.f) ? u : 0.2f * u;  // leaky_relu
                part[h] = fmaf(u, attv[h][j], part[h]);
            }
        }
#pragma unroll
        for (int h = 0; h < NH; ++h) {
            float e = part[h];
#pragma unroll
            for (int off = 16; off > 0; off >>= 1) e += __shfl_xor_sync(0xffffffffu, e, off);
            if (e > mh[h]) {
                float sc = __expf(mh[h] - e);
                dh[h] *= sc;
#pragma unroll
                for (int j = 0; j < NJ; ++j) acc[h][j] *= sc;
                mh[h] = e;
                dh[h] += 1.f;
#pragma unroll
                for (int j = 0; j < NJ; ++j) acc[h][j] += xs[h][j];
            } else {
                float w = __expf(e - mh[h]);
                dh[h] += w;
#pragma unroll
                for (int j = 0; j < NJ; ++j) acc[h][j] = fmaf(w, xs[h][j], acc[h][j]);
            }
        }
    }

#pragma unroll
    for (int h = 0; h < NH; ++h) {
        float inv = 1.f / dh[h];
#pragma unroll
        for (int j = 0; j < NJ; ++j) {
            int c = lane + 32 * j;
            if (c < CH) {
                int f = h * CH + c;
                float v = acc[h][j] * inv + bias[f] + resid[(size_t)i * ldr + f];
                if (res_b) v += res_b[f];
                v = (v - bn_m[f]) * rsqrtf(bn_v[f] + 1e-5f) * bn_g[f] + bn_b[f];
                if (do_relu) v = fmaxf(v, 0.f);
                out[(size_t)i * ldo + f] = v;
            }
        }
    }
}

// ---------------- host launch ---------------------------------------------
extern "C" void kernel_launch(void* const* d_in, const int* in_sizes, int n_in,
                              void* d_out, int out_size) {
    const float* x = (const float*)d_in[0];
    const int* ei = (const int*)d_in[1];
    const float* w1_src = (const float*)d_in[2];
    const float* w1_dst = (const float*)d_in[3];
    const float* att1 = (const float*)d_in[4];
    const float* b1 = (const float*)d_in[5];
    const float* bn1_g = (const float*)d_in[6];
    const float* bn1_b = (const float*)d_in[7];
    const float* bn1_m = (const float*)d_in[8];
    const float* bn1_v = (const float*)d_in[9];
    const float* res0_w = (const float*)d_in[10];
    const float* res0_b = (const float*)d_in[11];
    const float* w2_src = (const float*)d_in[12];
    const float* w2_dst = (const float*)d_in[13];
    const float* att2 = (const float*)d_in[14];
    const float* b2 = (const float*)d_in[15];
    const float* bn2_g = (const float*)d_in[16];
    const float* bn2_b = (const float*)d_in[17];
    const float* bn2_m = (const float*)d_in[18];
    const float* bn2_v = (const float*)d_in[19];
    const float* w3_src = (const float*)d_in[20];
    const float* w3_dst = (const float*)d_in[21];
    const float* att3 = (const float*)d_in[22];
    const float* b3 = (const float*)d_in[23];
    const float* bn3_g = (const float*)d_in[24];
    const float* bn3_b = (const float*)d_in[25];
    const float* bn3_m = (const float*)d_in[26];
    const float* bn3_v = (const float*)d_in[27];
    const float* res2_w = (const float*)d_in[28];
    const float* res2_b = (const float*)d_in[29];

    int n = in_sizes[0] / 100;
    int e = in_sizes[1] / 2;
    if (n > NN) n = NN;
    if (e > EE) e = EE;
    const int* srcp = ei;
    const int* dstp = ei + e;

    float *g1, *h1, *g2, *h2, *g3, *w1b, *w2b, *w3b;
    int *cnt, *offs, *cur, *csr;
    cudaGetSymbolAddress((void**)&g1, g_g1);
    cudaGetSymbolAddress((void**)&h1, g_h1);
    cudaGetSymbolAddress((void**)&g2, g_g2);
    cudaGetSymbolAddress((void**)&h2, g_h2);
    cudaGetSymbolAddress((void**)&g3, g_g3);
    cudaGetSymbolAddress((void**)&w1b, g_w1);
    cudaGetSymbolAddress((void**)&w2b, g_w2);
    cudaGetSymbolAddress((void**)&w3b, g_w3);
    cudaGetSymbolAddress((void**)&cnt, g_cnt);
    cudaGetSymbolAddress((void**)&offs, g_offs);
    cudaGetSymbolAddress((void**)&cur, g_cur);
    cudaGetSymbolAddress((void**)&csr, g_csr);

    // CSR build (by destination)
    cudaMemsetAsync(cnt, 0, (size_t)n * sizeof(int));
    hist_kernel<<<(e + 255) / 256, 256>>>(dstp, cnt, e);
    scan_kernel<<<1, 1024>>>(cnt, offs, cur, n);
    scatter_kernel<<<(e + 255) / 256, 256>>>(srcp, dstp, cur, csr, e);

    int gatBlocks = (n + 7) / 8;  // 8 warps / block
    int rowsB = (n + 127) / 128;

    // ----- layer 1: x[100] -> [xl1|xr1|res] (384 cols) -----
    pack3_kernel<<<64, 256>>>(w1b, w1_src, w1_dst, res0_w, 100, 128, 128, 128);
    sgemm_kernel<<<dim3(3, rowsB), 256>>>(x, w1b, g1, n, 384, 100);
    gat_kernel<4, 32><<<gatBlocks, 256>>>(g1, 384, att1, b1,
                                          g1 + 256, 384, res0_b,
                                          bn1_g, bn1_b, bn1_m, bn1_v,
                                          h1, 128, 1, offs, csr, n);

    // ----- layer 2: h1[128] -> [xl2|xr2] (256 cols), identity residual -----
    pack3_kernel<<<64, 256>>>(w2b, w2_src, w2_dst, nullptr, 128, 128, 128, 0);
    sgemm_kernel<<<dim3(2, rowsB), 256>>>(h1, w2b, g2, n, 256, 128);
    gat_kernel<4, 32><<<gatBlocks, 256>>>(g2, 256, att2, b2,
                                          h1, 128, nullptr,
                                          bn2_g, bn2_b, bn2_m, bn2_v,
                                          h2, 128, 1, offs, csr, n);

    // ----- layer 3: h2[128] -> [xl3|xr3|res] (141 cols), heads=1, no relu -----
    pack3_kernel<<<64, 256>>>(w3b, w3_src, w3_dst, res2_w, 128, 47, 47, 47);
    sgemm_kernel<<<dim3(2, rowsB), 256>>>(h2, w3b, g3, n, 141, 128);
    gat_kernel<1, 47><<<gatBlocks, 256>>>(g3, 141, att3, b3,
                                          g3 + 94, 141, res2_b,
                                          bn3_g, bn3_b, bn3_m, bn3_v,
                                          (float*)d_out, 47, 0, offs, csr, n);
}

// round 3
// speedup vs baseline: 1.4640x; 1.4640x over previous
#include <cuda_runtime.h>
#include <math.h>
#include <stdint.h>

// Problem constants (fixed by the dataset)
#define NN 50000
#define EE 800000

// ---------------- scratch (static device globals; no allocation) ----------
__device__ float g_g1[(size_t)NN * 384];  // [xl1 | xr1 | res1]
__device__ float g_h1[(size_t)NN * 128];
__device__ float g_g2[(size_t)NN * 256];  // [xl2 | xr2]
__device__ float g_h2[(size_t)NN * 128];
__device__ float g_g3[(size_t)NN * 144];  // [xl3 | xr3 | res3 | pad]
__device__ float g_w1[100 * 384];
__device__ float g_w2[128 * 256];
__device__ float g_w3[128 * 144];
__device__ int g_cnt[NN];
__device__ int g_offs[NN + 1];
__device__ int g_cur[NN];
__device__ int g_csr[EE];

// ---------------- CSR construction ----------------------------------------
__global__ void hist_kernel(const int* __restrict__ dst, int* __restrict__ cnt, int e) {
    int i = blockIdx.x * blockDim.x + threadIdx.x;
    if (i < e) atomicAdd(&cnt[dst[i]], 1);
}

__global__ void scan_kernel(const int* __restrict__ cnt, int* __restrict__ offs,
                            int* __restrict__ cur, int n) {
    const int T = 1024;
    int tid = threadIdx.x;
    int chunk = (n + T - 1) / T;
    int start = tid * chunk;
    int end = min(start + chunk, n);
    int s = 0;
    for (int i = start; i < end; ++i) s += cnt[i];
    __shared__ int sh[T];
    sh[tid] = s;
    __syncthreads();
    for (int off = 1; off < T; off <<= 1) {
        int t = 0;
        if (tid >= off) t = sh[tid - off];
        __syncthreads();
        if (tid >= off) sh[tid] += t;
        __syncthreads();
    }
    int incl = sh[tid];
    int run = incl - s;  // exclusive
    for (int i = start; i < end; ++i) {
        offs[i] = run;
        cur[i] = run;
        run += cnt[i];
    }
    if (tid == T - 1) offs[n] = run;
}

__global__ void scatter_kernel(const int* __restrict__ src, const int* __restrict__ dst,
                               int* __restrict__ cur, int* __restrict__ csr, int e) {
    int i = blockIdx.x * blockDim.x + threadIdx.x;
    if (i < e) {
        int p = atomicAdd(&cur[dst[i]], 1);
        csr[p] = src[i];
    }
}

// ---------------- weight packing with optional zero padding ---------------
// dst[k*Cp + c] = concat(a,b,c)[k][c], zero for c >= Ca+Cb+Cc
__global__ void pack3_kernel(float* __restrict__ dstp,
                             const float* __restrict__ a, const float* __restrict__ b,
                             const float* __restrict__ c,
                             int K, int Ca, int Cb, int Cc, int Cp) {
    int total = K * Cp;
    for (int idx = blockIdx.x * blockDim.x + threadIdx.x; idx < total;
         idx += gridDim.x * blockDim.x) {
        int k = idx / Cp;
        int col = idx - k * Cp;
        float v = 0.f;
        if (col < Ca) v = a[k * Ca + col];
        else if (col < Ca + Cb) v = b[k * Cb + (col - Ca)];
        else if (col < Ca + Cb + Cc) v = c[k * Cc + (col - Ca - Cb)];
        dstp[idx] = v;
    }
}

// ---------------- TF32 tensor-core GEMM: C[M,N] = A[M,K] @ B[K,N] ---------
// Requirements: K % 4 == 0, N % 4 == 0 (row starts 16B aligned).
__device__ __forceinline__ uint32_t f2tf32(float f) {
    uint32_t u;
    asm("cvt.rna.tf32.f32 %0, %1;" : "=r"(u) : "f"(f));
    return u;
}

__global__ void __launch_bounds__(256)
sgemm_tf32_kernel(const float* __restrict__ A, const float* __restrict__ B,
                  float* __restrict__ C, int M, int N, int K) {
    // Tiles: BM=128, BN=128, BK=32. 8 warps, each 32(M) x 64(N).
    __shared__ uint32_t As[128][36];   // [m][k], bank = (4m+k) mod 32 -> conflict-free frags
    __shared__ uint32_t Bs[32][136];   // [k][n], bank = (8k+n) mod 32 -> conflict-free frags

    const int t = threadIdx.x;
    const int lane = t & 31;
    const int warp = t >> 5;
    const int brow = blockIdx.y * 128;
    const int bcol = blockIdx.x * 128;
    const int wm = (warp >> 1) * 32;   // warp M offset (0,32,64,96)
    const int wn = (warp & 1) * 64;    // warp N offset (0,64)
    const int qm = lane >> 2;          // 0..7
    const int qk = lane & 3;           // 0..3

    float acc[2][8][4];
#pragma unroll
    for (int mi = 0; mi < 2; ++mi)
#pragma unroll
        for (int ni = 0; ni < 8; ++ni)
#pragma unroll
            for (int q = 0; q < 4; ++q) acc[mi][ni][q] = 0.f;

    // Global->smem load mappings
    const int a_kg = t & 7;    // float4 group in K (0..7 -> k 0..31)
    const int a_m0 = t >> 3;   // 0..31
    const int b_nc = t & 31;   // float4 group in N (0..31 -> n 0..127)
    const int b_k0 = t >> 5;   // 0..7

    for (int k0 = 0; k0 < K; k0 += 32) {
        // Load A tile 128x32
#pragma unroll
        for (int it = 0; it < 4; ++it) {
            int m = a_m0 + 32 * it;
            int grow = brow + m;
            int gk = k0 + a_kg * 4;
            float4 v = make_float4(0.f, 0.f, 0.f, 0.f);
            if (grow < M && gk < K)
                v = *reinterpret_cast<const float4*>(&A[(size_t)grow * K + gk]);
            As[m][a_kg * 4 + 0] = f2tf32(v.x);
            As[m][a_kg * 4 + 1] = f2tf32(v.y);
            As[m][a_kg * 4 + 2] = f2tf32(v.z);
            As[m][a_kg * 4 + 3] = f2tf32(v.w);
        }
        // Load B tile 32x128
#pragma unroll
        for (int it = 0; it < 4; ++it) {
            int kr = b_k0 + 8 * it;
            int gk = k0 + kr;
            int gn = bcol + b_nc * 4;
            float4 v = make_float4(0.f, 0.f, 0.f, 0.f);
            if (gk < K && gn < N)
                v = *reinterpret_cast<const float4*>(&B[(size_t)gk * N + gn]);
            Bs[kr][b_nc * 4 + 0] = f2tf32(v.x);
            Bs[kr][b_nc * 4 + 1] = f2tf32(v.y);
            Bs[kr][b_nc * 4 + 2] = f2tf32(v.z);
            Bs[kr][b_nc * 4 + 3] = f2tf32(v.w);
        }
        __syncthreads();

#pragma unroll
        for (int kk = 0; kk < 4; ++kk) {
            const int kb = kk * 8;
            uint32_t af[2][4];
#pragma unroll
            for (int mi = 0; mi < 2; ++mi) {
                int mr = wm + mi * 16 + qm;
                af[mi][0] = As[mr][kb + qk];
                af[mi][1] = As[mr + 8][kb + qk];
                af[mi][2] = As[mr][kb + qk + 4];
                af[mi][3] = As[mr + 8][kb + qk + 4];
            }
            uint32_t bf[8][2];
#pragma unroll
            for (int ni = 0; ni < 8; ++ni) {
                int nc = wn + ni * 8 + qm;
                bf[ni][0] = Bs[kb + qk][nc];
                bf[ni][1] = Bs[kb + qk + 4][nc];
            }
#pragma unroll
            for (int mi = 0; mi < 2; ++mi)
#pragma unroll
                for (int ni = 0; ni < 8; ++ni) {
                    asm volatile(
                        "mma.sync.aligned.m16n8k8.row.col.f32.tf32.tf32.f32 "
                        "{%0,%1,%2,%3}, {%4,%5,%6,%7}, {%8,%9}, {%0,%1,%2,%3};"
                        : "+f"(acc[mi][ni][0]), "+f"(acc[mi][ni][1]),
                          "+f"(acc[mi][ni][2]), "+f"(acc[mi][ni][3])
                        : "r"(af[mi][0]), "r"(af[mi][1]), "r"(af[mi][2]), "r"(af[mi][3]),
                          "r"(bf[ni][0]), "r"(bf[ni][1]));
                }
        }
        __syncthreads();
    }

    // Store (float2 per fragment half-row; n offsets are even -> 8B aligned)
#pragma unroll
    for (int mi = 0; mi < 2; ++mi) {
#pragma unroll
        for (int ni = 0; ni < 8; ++ni) {
            int r0 = brow + wm + mi * 16 + qm;
            int cc = bcol + wn + ni * 8 + 2 * qk;
            if (cc + 1 < N) {
                if (r0 < M)
                    *reinterpret_cast<float2*>(&C[(size_t)r0 * N + cc]) =
                        make_float2(acc[mi][ni][0], acc[mi][ni][1]);
                if (r0 + 8 < M)
                    *reinterpret_cast<float2*>(&C[(size_t)(r0 + 8) * N + cc]) =
                        make_float2(acc[mi][ni][2], acc[mi][ni][3]);
            } else if (cc < N) {
                if (r0 < M) C[(size_t)r0 * N + cc] = acc[mi][ni][0];
                if (r0 + 8 < M) C[(size_t)(r0 + 8) * N + cc] = acc[mi][ni][2];
            }
        }
    }
}

// ---------------- GATv2 edge phase: one warp per destination node ---------
template <int NH, int CH>
__global__ void gat_kernel(const float* __restrict__ xlr, int ld,
                           const float* __restrict__ att,
                           const float* __restrict__ bias,
                           const float* __restrict__ resid, int ldr,
                           const float* __restrict__ res_b,
                           const float* __restrict__ bn_g, const float* __restrict__ bn_b,
                           const float* __restrict__ bn_m, const float* __restrict__ bn_v,
                           float* __restrict__ out, int ldo, int do_relu,
                           const int* __restrict__ offs, const int* __restrict__ csr,
                           int n) {
    int warp = (blockIdx.x * blockDim.x + threadIdx.x) >> 5;
    int lane = threadIdx.x & 31;
    if (warp >= n) return;
    const int i = warp;
    constexpr int NJ = (CH + 31) / 32;
    constexpr int F = NH * CH;
    const float* xl = xlr;
    const float* xr = xlr + F;

    float xrv[NH][NJ], attv[NH][NJ], acc[NH][NJ], mh[NH], dh[NH];
#pragma unroll
    for (int h = 0; h < NH; ++h) {
        mh[h] = -INFINITY;
        dh[h] = 0.f;
#pragma unroll
        for (int j = 0; j < NJ; ++j) {
            int c = lane + 32 * j;
            bool ok = (c < CH);
            xrv[h][j] = ok ? xr[(size_t)i * ld + h * CH + c] : 0.f;
            attv[h][j] = ok ? att[h * CH + c] : 0.f;
            acc[h][j] = 0.f;
        }
    }

    int e0 = offs[i], e1 = offs[i + 1];
    for (int t = e0; t <= e1; ++t) {  // t == e1 -> implicit self-loop
        int s = (t < e1) ? csr[t] : i;
        float xs[NH][NJ], part[NH];
#pragma unroll
        for (int h = 0; h < NH; ++h) {
            part[h] = 0.f;
#pragma unroll
            for (int j = 0; j < NJ; ++j) {
                int c = lane + 32 * j;
                float v = (c < CH) ? xl[(size_t)s * ld + h * CH + c] : 0.f;
                xs[h][j] = v;
                float u = v + xrv[h][j];
                u = (u > 0.f) ? u : 0.2f * u;  // leaky_relu
                part[h] = fmaf(u, attv[h][j], part[h]);
            }
        }
#pragma unroll
        for (int h = 0; h < NH; ++h) {
            float e = part[h];
#pragma unroll
            for (int off = 16; off > 0; off >>= 1) e += __shfl_xor_sync(0xffffffffu, e, off);
            if (e > mh[h]) {
                float sc = __expf(mh[h] - e);
                dh[h] *= sc;
#pragma unroll
                for (int j = 0; j < NJ; ++j) acc[h][j] *= sc;
                mh[h] = e;
                dh[h] += 1.f;
#pragma unroll
                for (int j = 0; j < NJ; ++j) acc[h][j] += xs[h][j];
            } else {
                float w = __expf(e - mh[h]);
                dh[h] += w;
#pragma unroll
                for (int j = 0; j < NJ; ++j) acc[h][j] = fmaf(w, xs[h][j], acc[h][j]);
            }
        }
    }

#pragma unroll
    for (int h = 0; h < NH; ++h) {
        float inv = 1.f / dh[h];
#pragma unroll
        for (int j = 0; j < NJ; ++j) {
            int c = lane + 32 * j;
            if (c < CH) {
                int f = h * CH + c;
                float v = acc[h][j] * inv + bias[f] + resid[(size_t)i * ldr + f];
                if (res_b) v += res_b[f];
                v = (v - bn_m[f]) * rsqrtf(bn_v[f] + 1e-5f) * bn_g[f] + bn_b[f];
                if (do_relu) v = fmaxf(v, 0.f);
                out[(size_t)i * ldo + f] = v;
            }
        }
    }
}

// ---------------- host launch ---------------------------------------------
extern "C" void kernel_launch(void* const* d_in, const int* in_sizes, int n_in,
                              void* d_out, int out_size) {
    const float* x = (const float*)d_in[0];
    const int* ei = (const int*)d_in[1];
    const float* w1_src = (const float*)d_in[2];
    const float* w1_dst = (const float*)d_in[3];
    const float* att1 = (const float*)d_in[4];
    const float* b1 = (const float*)d_in[5];
    const float* bn1_g = (const float*)d_in[6];
    const float* bn1_b = (const float*)d_in[7];
    const float* bn1_m = (const float*)d_in[8];
    const float* bn1_v = (const float*)d_in[9];
    const float* res0_w = (const float*)d_in[10];
    const float* res0_b = (const float*)d_in[11];
    const float* w2_src = (const float*)d_in[12];
    const float* w2_dst = (const float*)d_in[13];
    const float* att2 = (const float*)d_in[14];
    const float* b2 = (const float*)d_in[15];
    const float* bn2_g = (const float*)d_in[16];
    const float* bn2_b = (const float*)d_in[17];
    const float* bn2_m = (const float*)d_in[18];
    const float* bn2_v = (const float*)d_in[19];
    const float* w3_src = (const float*)d_in[20];
    const float* w3_dst = (const float*)d_in[21];
    const float* att3 = (const float*)d_in[22];
    const float* b3 = (const float*)d_in[23];
    const float* bn3_g = (const float*)d_in[24];
    const float* bn3_b = (const float*)d_in[25];
    const float* bn3_m = (const float*)d_in[26];
    const float* bn3_v = (const float*)d_in[27];
    const float* res2_w = (const float*)d_in[28];
    const float* res2_b = (const float*)d_in[29];

    int n = in_sizes[0] / 100;
    int e = in_sizes[1] / 2;
    if (n > NN) n = NN;
    if (e > EE) e = EE;
    const int* srcp = ei;
    const int* dstp = ei + e;

    float *g1, *h1, *g2, *h2, *g3, *w1b, *w2b, *w3b;
    int *cnt, *offs, *cur, *csr;
    cudaGetSymbolAddress((void**)&g1, g_g1);
    cudaGetSymbolAddress((void**)&h1, g_h1);
    cudaGetSymbolAddress((void**)&g2, g_g2);
    cudaGetSymbolAddress((void**)&h2, g_h2);
    cudaGetSymbolAddress((void**)&g3, g_g3);
    cudaGetSymbolAddress((void**)&w1b, g_w1);
    cudaGetSymbolAddress((void**)&w2b, g_w2);
    cudaGetSymbolAddress((void**)&w3b, g_w3);
    cudaGetSymbolAddress((void**)&cnt, g_cnt);
    cudaGetSymbolAddress((void**)&offs, g_offs);
    cudaGetSymbolAddress((void**)&cur, g_cur);
    cudaGetSymbolAddress((void**)&csr, g_csr);

    // CSR build (by destination)
    cudaMemsetAsync(cnt, 0, (size_t)n * sizeof(int));
    hist_kernel<<<(e + 255) / 256, 256>>>(dstp, cnt, e);
    scan_kernel<<<1, 1024>>>(cnt, offs, cur, n);
    scatter_kernel<<<(e + 255) / 256, 256>>>(srcp, dstp, cur, csr, e);

    int gatBlocks = (n + 7) / 8;  // 8 warps / block
    int rowsB = (n + 127) / 128;

    // ----- layer 1: x[100] -> [xl1|xr1|res] (384 cols) -----
    pack3_kernel<<<64, 256>>>(w1b, w1_src, w1_dst, res0_w, 100, 128, 128, 128, 384);
    sgemm_tf32_kernel<<<dim3(3, rowsB), 256>>>(x, w1b, g1, n, 384, 100);
    gat_kernel<4, 32><<<gatBlocks, 256>>>(g1, 384, att1, b1,
                                          g1 + 256, 384, res0_b,
                                          bn1_g, bn1_b, bn1_m, bn1_v,
                                          h1, 128, 1, offs, csr, n);

    // ----- layer 2: h1[128] -> [xl2|xr2] (256 cols), identity residual -----
    pack3_kernel<<<64, 256>>>(w2b, w2_src, w2_dst, nullptr, 128, 128, 128, 0, 256);
    sgemm_tf32_kernel<<<dim3(2, rowsB), 256>>>(h1, w2b, g2, n, 256, 128);
    gat_kernel<4, 32><<<gatBlocks, 256>>>(g2, 256, att2, b2,
                                          h1, 128, nullptr,
                                          bn2_g, bn2_b, bn2_m, bn2_v,
                                          h2, 128, 1, offs, csr, n);

    // ----- layer 3: h2[128] -> [xl3|xr3|res|pad] (144 cols), heads=1, no relu -----
    pack3_kernel<<<64, 256>>>(w3b, w3_src, w3_dst, res2_w, 128, 47, 47, 47, 144);
    sgemm_tf32_kernel<<<dim3(2, rowsB), 256>>>(h2, w3b, g3, n, 144, 128);
    gat_kernel<1, 47><<<gatBlocks, 256>>>(g3, 144, att3, b3,
                                          g3 + 94, 144, res2_b,
                                          bn3_g, bn3_b, bn3_m, bn3_v,
                                          (float*)d_out, 47, 0, offs, csr, n);
}

// round 4
// speedup vs baseline: 2.1674x; 1.4805x over previous
#include <cuda_runtime.h>
#include <math.h>
#include <stdint.h>

// Problem constants (fixed by the dataset)
#define NN 50000
#define EE 800000

// ---------------- scratch (static device globals; no allocation) ----------
__device__ float g_g1[(size_t)NN * 384];  // [xl1 | xr1 | res1]
__device__ float g_h1[(size_t)NN * 128];
__device__ float g_g2[(size_t)NN * 256];  // [xl2 | xr2]
__device__ float g_h2[(size_t)NN * 128];
__device__ float g_g3[(size_t)NN * 144];  // [xl3 | xr3 | res3 | pad]
__device__ float g_w1[100 * 384];
__device__ float g_w2[128 * 256];
__device__ float g_w3[128 * 144];
__device__ int g_cnt[NN];
__device__ int g_offs[NN + 1];
__device__ int g_cur[NN];
__device__ int g_csr[EE];

// ---------------- CSR construction ----------------------------------------
__global__ void hist_kernel(const int* __restrict__ dst, int* __restrict__ cnt, int e) {
    int i = blockIdx.x * blockDim.x + threadIdx.x;
    if (i < e) atomicAdd(&cnt[dst[i]], 1);
}

__global__ void scan_kernel(const int* __restrict__ cnt, int* __restrict__ offs,
                            int* __restrict__ cur, int n) {
    const int T = 1024;
    int tid = threadIdx.x;
    int chunk = (n + T - 1) / T;
    int start = tid * chunk;
    int end = min(start + chunk, n);
    int s = 0;
    for (int i = start; i < end; ++i) s += cnt[i];
    __shared__ int sh[T];
    sh[tid] = s;
    __syncthreads();
    for (int off = 1; off < T; off <<= 1) {
        int t = 0;
        if (tid >= off) t = sh[tid - off];
        __syncthreads();
        if (tid >= off) sh[tid] += t;
        __syncthreads();
    }
    int incl = sh[tid];
    int run = incl - s;  // exclusive
    for (int i = start; i < end; ++i) {
        offs[i] = run;
        cur[i] = run;
        run += cnt[i];
    }
    if (tid == T - 1) offs[n] = run;
}

__global__ void scatter_kernel(const int* __restrict__ src, const int* __restrict__ dst,
                               int* __restrict__ cur, int* __restrict__ csr, int e) {
    int i = blockIdx.x * blockDim.x + threadIdx.x;
    if (i < e) {
        int p = atomicAdd(&cur[dst[i]], 1);
        csr[p] = src[i];
    }
}

// ---------------- weight packing with optional zero padding ---------------
__global__ void pack3_kernel(float* __restrict__ dstp,
                             const float* __restrict__ a, const float* __restrict__ b,
                             const float* __restrict__ c,
                             int K, int Ca, int Cb, int Cc, int Cp) {
    int total = K * Cp;
    for (int idx = blockIdx.x * blockDim.x + threadIdx.x; idx < total;
         idx += gridDim.x * blockDim.x) {
        int k = idx / Cp;
        int col = idx - k * Cp;
        float v = 0.f;
        if (col < Ca) v = a[k * Ca + col];
        else if (col < Ca + Cb) v = b[k * Cb + (col - Ca)];
        else if (col < Ca + Cb + Cc) v = c[k * Cc + (col - Ca - Cb)];
        dstp[idx] = v;
    }
}

// ---------------- TF32 tensor-core GEMM with fragment-order smem ----------
__device__ __forceinline__ uint32_t f2tf32(float f) {
    uint32_t u;
    asm("cvt.rna.tf32.f32 %0, %1;" : "=r"(u) : "f"(f));
    return u;
}

// Af[mt][kt][lane*4 + idx]: thread's full A-fragment contiguous (1x LDS.128)
// Bf[kt][lane*36 + nt*2 + slot]: per-lane 16 n-tiles contiguous (2x LDS.128)
__global__ void __launch_bounds__(256, 2)
sgemm_tf32_kernel(const float* __restrict__ A, const float* __restrict__ B,
                  float* __restrict__ C, int M, int N, int K) {
    __shared__ uint32_t Af[8][4][128];   // 16 KB
    __shared__ uint32_t Bf[4][1152];     // 18 KB (lane stride 36)

    const int t = threadIdx.x;
    const int lane = t & 31;
    const int warp = t >> 5;
    const int brow = blockIdx.y * 128;
    const int bcol = blockIdx.x * 128;
    const int wm = (warp >> 1) * 32;   // 0,32,64,96
    const int wn = (warp & 1) * 64;    // 0,64
    const int qm = lane >> 2;          // 0..7
    const int qk = lane & 3;           // 0..3

    float acc[2][8][4];
#pragma unroll
    for (int mi = 0; mi < 2; ++mi)
#pragma unroll
        for (int ni = 0; ni < 8; ++ni)
#pragma unroll
            for (int q = 0; q < 4; ++q) acc[mi][ni][q] = 0.f;

    const int a_m0 = t >> 3;   // 0..31
    const int a_kg = t & 7;    // k group of 4 (0..7)
    const int b_n0 = (t & 31) * 4;
    const int b_k0 = t >> 5;   // 0..7

    const int a_kt = a_kg >> 1;
    const int a_ik = a_kg & 1;

    for (int k0 = 0; k0 < K; k0 += 32) {
        // ---- fill A in fragment order ----
#pragma unroll
        for (int it = 0; it < 4; ++it) {
            int m = a_m0 + 32 * it;
            int grow = brow + m;
            int gk = k0 + a_kg * 4;
            float4 v = make_float4(0.f, 0.f, 0.f, 0.f);
            if (grow < M && gk < K)
                v = *reinterpret_cast<const float4*>(&A[(size_t)grow * K + gk]);
            int mt = m >> 4;
            int qmw = m & 7;
            int idx = ((m >> 3) & 1) + 2 * a_ik;
            uint32_t* dst = &Af[mt][a_kt][0];
            dst[(qmw * 4 + 0) * 4 + idx] = f2tf32(v.x);
            dst[(qmw * 4 + 1) * 4 + idx] = f2tf32(v.y);
            dst[(qmw * 4 + 2) * 4 + idx] = f2tf32(v.z);
            dst[(qmw * 4 + 3) * 4 + idx] = f2tf32(v.w);
        }
        // ---- fill B in fragment order ----
#pragma unroll
        for (int it = 0; it < 4; ++it) {
            int kr = b_k0 + 8 * it;
            int gk = k0 + kr;
            int gn = bcol + b_n0;
            float4 v = make_float4(0.f, 0.f, 0.f, 0.f);
            if (gk < K && gn < N)
                v = *reinterpret_cast<const float4*>(&B[(size_t)gk * N + gn]);
            int kt = kr >> 3;
            int qkb = kr & 3;
            int slot = (kr >> 2) & 1;
            uint32_t* dst = &Bf[kt][0];
            float vv[4] = {v.x, v.y, v.z, v.w};
#pragma unroll
            for (int j = 0; j < 3 + 1; ++j) {
                int nn = b_n0 + j;
                int nt = nn >> 3;
                int qmb = nn & 7;
                dst[(qmb * 4 + qkb) * 36 + nt * 2 + slot] = f2tf32(vv[j]);
            }
        }
        __syncthreads();

#pragma unroll
        for (int kk = 0; kk < 4; ++kk) {
            uint32_t af[2][4];
            *reinterpret_cast<uint4*>(af[0]) =
                *reinterpret_cast<const uint4*>(&Af[wm >> 4][kk][lane * 4]);
            *reinterpret_cast<uint4*>(af[1]) =
                *reinterpret_cast<const uint4*>(&Af[(wm >> 4) + 1][kk][lane * 4]);
            uint32_t bfv[8][2];
            const uint32_t* bp = &Bf[kk][lane * 36 + (wn >> 2)];
            *reinterpret_cast<uint4*>(&bfv[0][0]) = *reinterpret_cast<const uint4*>(bp);
            *reinterpret_cast<uint4*>(&bfv[2][0]) = *reinterpret_cast<const uint4*>(bp + 4);
            *reinterpret_cast<uint4*>(&bfv[4][0]) = *reinterpret_cast<const uint4*>(bp + 8);
            *reinterpret_cast<uint4*>(&bfv[6][0]) = *reinterpret_cast<const uint4*>(bp + 12);
#pragma unroll
            for (int mi = 0; mi < 2; ++mi)
#pragma unroll
                for (int ni = 0; ni < 8; ++ni) {
                    asm volatile(
                        "mma.sync.aligned.m16n8k8.row.col.f32.tf32.tf32.f32 "
                        "{%0,%1,%2,%3}, {%4,%5,%6,%7}, {%8,%9}, {%0,%1,%2,%3};"
                        : "+f"(acc[mi][ni][0]), "+f"(acc[mi][ni][1]),
                          "+f"(acc[mi][ni][2]), "+f"(acc[mi][ni][3])
                        : "r"(af[mi][0]), "r"(af[mi][1]), "r"(af[mi][2]), "r"(af[mi][3]),
                          "r"(bfv[ni][0]), "r"(bfv[ni][1]));
                }
        }
        __syncthreads();
    }

#pragma unroll
    for (int mi = 0; mi < 2; ++mi) {
#pragma unroll
        for (int ni = 0; ni < 8; ++ni) {
            int r0 = brow + wm + mi * 16 + qm;
            int cc = bcol + wn + ni * 8 + 2 * qk;
            if (cc + 1 < N) {
                if (r0 < M)
                    *reinterpret_cast<float2*>(&C[(size_t)r0 * N + cc]) =
                        make_float2(acc[mi][ni][0], acc[mi][ni][1]);
                if (r0 + 8 < M)
                    *reinterpret_cast<float2*>(&C[(size_t)(r0 + 8) * N + cc]) =
                        make_float2(acc[mi][ni][2], acc[mi][ni][3]);
            } else if (cc < N) {
                if (r0 < M) C[(size_t)r0 * N + cc] = acc[mi][ni][0];
                if (r0 + 8 < M) C[(size_t)(r0 + 8) * N + cc] = acc[mi][ni][2];
            }
        }
    }
}

// ---------------- GATv2 4-head edge kernel: 8 lanes per head ---------------
// lane l: head h = l>>3, channels h*32 + (l&7)*4 .. +3  == floats [4l, 4l+3]
__global__ void gat4_kernel(const float* __restrict__ xlr, int ld,
                            const float* __restrict__ att,
                            const float* __restrict__ bias,
                            const float* __restrict__ resid, int ldr,
                            const float* __restrict__ res_b,
                            const float* __restrict__ bn_g, const float* __restrict__ bn_b,
                            const float* __restrict__ bn_m, const float* __restrict__ bn_v,
                            float* __restrict__ out, int do_relu,
                            const int* __restrict__ offs, const int* __restrict__ csr,
                            int n) {
    int warp = (blockIdx.x * blockDim.x + threadIdx.x) >> 5;
    int lane = threadIdx.x & 31;
    if (warp >= n) return;
    const int i = warp;

    const float4 xrv = reinterpret_cast<const float4*>(xlr + (size_t)i * ld + 128)[lane];
    const float4 attv = reinterpret_cast<const float4*>(att)[lane];

    float m = -INFINITY, d = 0.f;
    float4 acc = make_float4(0.f, 0.f, 0.f, 0.f);

    int e0 = offs[i];
    int deg = offs[i + 1] - e0;

    int s = (deg > 0) ? csr[e0] : i;
    float4 v = reinterpret_cast<const float4*>(xlr + (size_t)s * ld)[lane];

    for (int t = 0; t <= deg; ++t) {
        float4 cur = v;
        if (t < deg) {
            int sn = (t + 1 < deg) ? csr[e0 + t + 1] : i;
            v = reinterpret_cast<const float4*>(xlr + (size_t)sn * ld)[lane];
        }
        float ux = cur.x + xrv.x, uy = cur.y + xrv.y,
              uz = cur.z + xrv.z, uw = cur.w + xrv.w;
        ux = (ux > 0.f) ? ux : 0.2f * ux;
        uy = (uy > 0.f) ? uy : 0.2f * uy;
        uz = (uz > 0.f) ? uz : 0.2f * uz;
        uw = (uw > 0.f) ? uw : 0.2f * uw;
        float p = fmaf(ux, attv.x, fmaf(uy, attv.y, fmaf(uz, attv.z, uw * attv.w)));
        p += __shfl_xor_sync(0xffffffffu, p, 1);
        p += __shfl_xor_sync(0xffffffffu, p, 2);
        p += __shfl_xor_sync(0xffffffffu, p, 4);
        float mnew = fmaxf(m, p);
        float sc = __expf(m - mnew);
        float w = __expf(p - mnew);
        d = d * sc + w;
        m = mnew;
        acc.x = fmaf(acc.x, sc, w * cur.x);
        acc.y = fmaf(acc.y, sc, w * cur.y);
        acc.z = fmaf(acc.z, sc, w * cur.z);
        acc.w = fmaf(acc.w, sc, w * cur.w);
    }

    float inv = 1.f / d;
    float4 bi = reinterpret_cast<const float4*>(bias)[lane];
    float4 rs = reinterpret_cast<const float4*>(resid + (size_t)i * ldr)[lane];
    float4 g = reinterpret_cast<const float4*>(bn_g)[lane];
    float4 bb = reinterpret_cast<const float4*>(bn_b)[lane];
    float4 mm = reinterpret_cast<const float4*>(bn_m)[lane];
    float4 vv = reinterpret_cast<const float4*>(bn_v)[lane];
    float4 o;
    o.x = acc.x * inv + bi.x + rs.x;
    o.y = acc.y * inv + bi.y + rs.y;
    o.z = acc.z * inv + bi.z + rs.z;
    o.w = acc.w * inv + bi.w + rs.w;
    if (res_b) {
        float4 rb = reinterpret_cast<const float4*>(res_b)[lane];
        o.x += rb.x; o.y += rb.y; o.z += rb.z; o.w += rb.w;
    }
    o.x = (o.x - mm.x) * rsqrtf(vv.x + 1e-5f) * g.x + bb.x;
    o.y = (o.y - mm.y) * rsqrtf(vv.y + 1e-5f) * g.y + bb.y;
    o.z = (o.z - mm.z) * rsqrtf(vv.z + 1e-5f) * g.z + bb.z;
    o.w = (o.w - mm.w) * rsqrtf(vv.w + 1e-5f) * g.w + bb.w;
    if (do_relu) {
        o.x = fmaxf(o.x, 0.f); o.y = fmaxf(o.y, 0.f);
        o.z = fmaxf(o.z, 0.f); o.w = fmaxf(o.w, 0.f);
    }
    reinterpret_cast<float4*>(out + (size_t)i * 128)[lane] = o;
}

// ---------------- generic GAT kernel (layer 3: heads=1, ch=47) -------------
template <int NH, int CH>
__global__ void gat_kernel(const float* __restrict__ xlr, int ld,
                           const float* __restrict__ att,
                           const float* __restrict__ bias,
                           const float* __restrict__ resid, int ldr,
                           const float* __restrict__ res_b,
                           const float* __restrict__ bn_g, const float* __restrict__ bn_b,
                           const float* __restrict__ bn_m, const float* __restrict__ bn_v,
                           float* __restrict__ out, int ldo, int do_relu,
                           const int* __restrict__ offs, const int* __restrict__ csr,
                           int n) {
    int warp = (blockIdx.x * blockDim.x + threadIdx.x) >> 5;
    int lane = threadIdx.x & 31;
    if (warp >= n) return;
    const int i = warp;
    constexpr int NJ = (CH + 31) / 32;
    constexpr int F = NH * CH;
    const float* xl = xlr;
    const float* xr = xlr + F;

    float xrv[NH][NJ], attv[NH][NJ], acc[NH][NJ], mh[NH], dh[NH];
#pragma unroll
    for (int h = 0; h < NH; ++h) {
        mh[h] = -INFINITY;
        dh[h] = 0.f;
#pragma unroll
        for (int j = 0; j < NJ; ++j) {
            int c = lane + 32 * j;
            bool ok = (c < CH);
            xrv[h][j] = ok ? xr[(size_t)i * ld + h * CH + c] : 0.f;
            attv[h][j] = ok ? att[h * CH + c] : 0.f;
            acc[h][j] = 0.f;
        }
    }

    int e0 = offs[i], e1 = offs[i + 1];
    for (int t = e0; t <= e1; ++t) {
        int s = (t < e1) ? csr[t] : i;
        float xs[NH][NJ], part[NH];
#pragma unroll
        for (int h = 0; h < NH; ++h) {
            part[h] = 0.f;
#pragma unroll
            for (int j = 0; j < NJ; ++j) {
                int c = lane + 32 * j;
                float v = (c < CH) ? xl[(size_t)s * ld + h * CH + c] : 0.f;
                xs[h][j] = v;
                float u = v + xrv[h][j];
                u = (u > 0.f) ? u : 0.2f * u;
                part[h] = fmaf(u, attv[h][j], part[h]);
            }
        }
#pragma unroll
        for (int h = 0; h < NH; ++h) {
            float e = part[h];
#pragma unroll
            for (int off = 16; off > 0; off >>= 1) e += __shfl_xor_sync(0xffffffffu, e, off);
            float mnew = fmaxf(mh[h], e);
            float sc = __expf(mh[h] - mnew);
            float w = __expf(e - mnew);
            dh[h] = dh[h] * sc + w;
            mh[h] = mnew;
#pragma unroll
            for (int j = 0; j < NJ; ++j) acc[h][j] = fmaf(acc[h][j], sc, w * xs[h][j]);
        }
    }

#pragma unroll
    for (int h = 0; h < NH; ++h) {
        float inv = 1.f / dh[h];
#pragma unroll
        for (int j = 0; j < NJ; ++j) {
            int c = lane + 32 * j;
            if (c < CH) {
                int f = h * CH + c;
                float v = acc[h][j] * inv + bias[f] + resid[(size_t)i * ldr + f];
                if (res_b) v += res_b[f];
                v = (v - bn_m[f]) * rsqrtf(bn_v[f] + 1e-5f) * bn_g[f] + bn_b[f];
                if (do_relu) v = fmaxf(v, 0.f);
                out[(size_t)i * ldo + f] = v;
            }
        }
    }
}

// ---------------- host launch ---------------------------------------------
extern "C" void kernel_launch(void* const* d_in, const int* in_sizes, int n_in,
                              void* d_out, int out_size) {
    const float* x = (const float*)d_in[0];
    const int* ei = (const int*)d_in[1];
    const float* w1_src = (const float*)d_in[2];
    const float* w1_dst = (const float*)d_in[3];
    const float* att1 = (const float*)d_in[4];
    const float* b1 = (const float*)d_in[5];
    const float* bn1_g = (const float*)d_in[6];
    const float* bn1_b = (const float*)d_in[7];
    const float* bn1_m = (const float*)d_in[8];
    const float* bn1_v = (const float*)d_in[9];
    const float* res0_w = (const float*)d_in[10];
    const float* res0_b = (const float*)d_in[11];
    const float* w2_src = (const float*)d_in[12];
    const float* w2_dst = (const float*)d_in[13];
    const float* att2 = (const float*)d_in[14];
    const float* b2 = (const float*)d_in[15];
    const float* bn2_g = (const float*)d_in[16];
    const float* bn2_b = (const float*)d_in[17];
    const float* bn2_m = (const float*)d_in[18];
    const float* bn2_v = (const float*)d_in[19];
    const float* w3_src = (const float*)d_in[20];
    const float* w3_dst = (const float*)d_in[21];
    const float* att3 = (const float*)d_in[22];
    const float* b3 = (const float*)d_in[23];
    const float* bn3_g = (const float*)d_in[24];
    const float* bn3_b = (const float*)d_in[25];
    const float* bn3_m = (const float*)d_in[26];
    const float* bn3_v = (const float*)d_in[27];
    const float* res2_w = (const float*)d_in[28];
    const float* res2_b = (const float*)d_in[29];

    int n = in_sizes[0] / 100;
    int e = in_sizes[1] / 2;
    if (n > NN) n = NN;
    if (e > EE) e = EE;
    const int* srcp = ei;
    const int* dstp = ei + e;

    float *g1, *h1, *g2, *h2, *g3, *w1b, *w2b, *w3b;
    int *cnt, *offs, *cur, *csr;
    cudaGetSymbolAddress((void**)&g1, g_g1);
    cudaGetSymbolAddress((void**)&h1, g_h1);
    cudaGetSymbolAddress((void**)&g2, g_g2);
    cudaGetSymbolAddress((void**)&h2, g_h2);
    cudaGetSymbolAddress((void**)&g3, g_g3);
    cudaGetSymbolAddress((void**)&w1b, g_w1);
    cudaGetSymbolAddress((void**)&w2b, g_w2);
    cudaGetSymbolAddress((void**)&w3b, g_w3);
    cudaGetSymbolAddress((void**)&cnt, g_cnt);
    cudaGetSymbolAddress((void**)&offs, g_offs);
    cudaGetSymbolAddress((void**)&cur, g_cur);
    cudaGetSymbolAddress((void**)&csr, g_csr);

    int gatBlocks = (n + 7) / 8;
    int rowsB = (n + 127) / 128;

    // Order chosen so gemm1 lands at ncu launch idx 5 (memset appears as 2).
    cudaMemsetAsync(cnt, 0, (size_t)n * sizeof(int));
    pack3_kernel<<<64, 256>>>(w1b, w1_src, w1_dst, res0_w, 100, 128, 128, 128, 384);
    pack3_kernel<<<64, 256>>>(w2b, w2_src, w2_dst, nullptr, 128, 128, 128, 0, 256);
    pack3_kernel<<<64, 256>>>(w3b, w3_src, w3_dst, res2_w, 128, 47, 47, 47, 144);
    sgemm_tf32_kernel<<<dim3(3, rowsB), 256>>>(x, w1b, g1, n, 384, 100);

    // CSR build (by destination)
    hist_kernel<<<(e + 255) / 256, 256>>>(dstp, cnt, e);
    scan_kernel<<<1, 1024>>>(cnt, offs, cur, n);
    scatter_kernel<<<(e + 255) / 256, 256>>>(srcp, dstp, cur, csr, e);

    // ----- layer 1 -----
    gat4_kernel<<<gatBlocks, 256>>>(g1, 384, att1, b1,
                                    g1 + 256, 384, res0_b,
                                    bn1_g, bn1_b, bn1_m, bn1_v,
                                    h1, 1, offs, csr, n);

    // ----- layer 2 -----
    sgemm_tf32_kernel<<<dim3(2, rowsB), 256>>>(h1, w2b, g2, n, 256, 128);
    gat4_kernel<<<gatBlocks, 256>>>(g2, 256, att2, b2,
                                    h1, 128, nullptr,
                                    bn2_g, bn2_b, bn2_m, bn2_v,
                                    h2, 1, offs, csr, n);

    // ----- layer 3 -----
    sgemm_tf32_kernel<<<dim3(2, rowsB), 256>>>(h2, w3b, g3, n, 144, 128);
    gat_kernel<1, 47><<<gatBlocks, 256>>>(g3, 144, att3, b3,
                                          g3 + 94, 144, res2_b,
                                          bn3_g, bn3_b, bn3_m, bn3_v,
                                          (float*)d_out, 47, 0, offs, csr, n);
}